// round 2
// baseline (speedup 1.0000x reference)
#include <cuda_runtime.h>
#include <cuda_bf16.h>

// DynamicMaskHead fused kernel (R2): P=2 column blocking to fix register
// pressure (R1 had 255 regs -> 12.5% occupancy, latency-bound).
//
// Shapes (fixed by the problem instance):
//   mask_feats_*   : [2, 8, 100, 152] f32
//   mask_head_params: [128, 419] f32
//   output         : 3 x [128, 1, 200, 304] f32, concatenated (b, e, f)

#define Hh   100
#define Wd   152
#define HWd  15200
#define OH   200
#define OW   304
#define OT   16      // output rows per block tile
#define LR   10      // max logits rows per tile (8 + halo)
#define NPAR 419

// One MLP head: 10 -> 8 (relu) -> 8 (relu, kept as x2) -> 1, P=2 positions.
__device__ __forceinline__ void run_head2(
    const float* __restrict__ w1, const float* __restrict__ b1,
    const float* __restrict__ w2, const float* __restrict__ b2,
    const float* __restrict__ w3, float b3,
    const float2 f[8], const float relx[2], float rely,
    float x2[8][2], float l[2])
{
    float x1[8][2];
#pragma unroll
    for (int c = 0; c < 8; c++) {
        const float* wr = w1 + c * 10;
        float a0 = fmaf(wr[0], relx[0], fmaf(wr[1], rely, b1[c]));
        float a1 = fmaf(wr[0], relx[1], fmaf(wr[1], rely, b1[c]));
#pragma unroll
        for (int k = 0; k < 8; k++) {
            const float w = wr[2 + k];
            a0 = fmaf(w, f[k].x, a0);
            a1 = fmaf(w, f[k].y, a1);
        }
        x1[c][0] = fmaxf(a0, 0.0f);
        x1[c][1] = fmaxf(a1, 0.0f);
    }
#pragma unroll
    for (int c = 0; c < 8; c++) {
        const float* wr = w2 + c * 8;
        float a0 = b2[c], a1 = b2[c];
#pragma unroll
        for (int k = 0; k < 8; k++) {
            const float w = wr[k];
            a0 = fmaf(w, x1[k][0], a0);
            a1 = fmaf(w, x1[k][1], a1);
        }
        x2[c][0] = fmaxf(a0, 0.0f);
        x2[c][1] = fmaxf(a1, 0.0f);
    }
    float l0 = b3, l1 = b3;
#pragma unroll
    for (int k = 0; k < 8; k++) {
        const float w = w3[k];
        l0 = fmaf(w, x2[k][0], l0);
        l1 = fmaf(w, x2[k][1], l1);
    }
    l[0] = l0; l[1] = l1;
}

__global__ void __launch_bounds__(256, 2)
dmh_kernel(const float* __restrict__ feats_b,
           const float* __restrict__ feats_e,
           const float* __restrict__ params,
           const float* __restrict__ locs,
           const float* __restrict__ soi_arr,
           const int*   __restrict__ im_inds,
           const int*   __restrict__ fpn,
           const int*   __restrict__ stride_ptr,
           float*       __restrict__ out,
           int n_inst)
{
    const int tid  = threadIdx.x;
    const int tile = blockIdx.x;
    const int inst = blockIdx.y;
    const int i0   = tile * OT;

    __shared__ float sp[NPAR];
    __shared__ float sl[3][LR][Wd];

    // cooperative param load for this instance
    const float* prow = params + inst * NPAR;
    for (int t = tid; t < NPAR; t += 256) sp[t] = prow[t];

    const int   stride  = stride_ptr ? *stride_ptr : 8;
    const float fstride = (float)stride;
    const float halfs   = (float)(stride >> 1);

    const float ix  = locs[inst * 2 + 0];
    const float iy  = locs[inst * 2 + 1];
    const float inv = 1.0f / soi_arr[fpn[inst]];
    const int   im  = im_inds[inst];

    // logits rows needed for output rows [i0, i0+OT)
    const int ybase = max(0, 8 * tile - 1);
    const int yend  = min(Hh - 1, 8 * tile + 8);
    const int nrows = yend - ybase + 1;

    __syncthreads();

    const float* w1b = sp;       const float* w2b = sp + 80;  const float* w3b = sp + 144;
    const float* b1b = sp + 152; const float* b2b = sp + 160; const float  b3b = sp[168];
    const float* w1e = sp + 169; const float* w2e = sp + 249; const float* w3e = sp + 313;
    const float* b1e = sp + 321; const float* b2e = sp + 329; const float  b3e = sp[337];
    const float* wf1 = sp + 338; const float* wf2 = sp + 402; const float* bf1 = sp + 410;
    const float  bf2 = sp[418];

    const float* fbB = feats_b + (long long)im * 8 * HWd;
    const float* fbE = feats_e + (long long)im * 8 * HWd;

    // ---------------- Phase B: compute logits strip into smem ----------------
    const int ngroups = nrows * (Wd / 2);   // 76 column-pairs per row
    for (int g = tid; g < ngroups; g += 256) {
        const int srow = g / 76;
        const int c0   = (g - srow * 76) * 2;
        const int y    = ybase + srow;

        const float rely = (iy - ((float)y * fstride + halfs)) * inv;
        float relx[2];
        relx[0] = (ix - ((float)c0 * fstride + halfs)) * inv;
        relx[1] = relx[0] - fstride * inv;

        const int base = y * Wd + c0;

        float2 f[8];
#pragma unroll
        for (int k = 0; k < 8; k++)
            f[k] = *(const float2*)(fbB + k * HWd + base);

        float x2b[8][2], lb[2];
        run_head2(w1b, b1b, w2b, b2b, w3b, b3b, f, relx, rely, x2b, lb);

#pragma unroll
        for (int k = 0; k < 8; k++)
            f[k] = *(const float2*)(fbE + k * HWd + base);

        float x2e[8][2], le[2];
        run_head2(w1e, b1e, w2e, b2e, w3e, b3e, f, relx, rely, x2e, le);

        // fused head: input = x2b + x2e (in-place into x2e), 8->8 (relu) -> 1
#pragma unroll
        for (int k = 0; k < 8; k++) {
            x2e[k][0] += x2b[k][0];
            x2e[k][1] += x2b[k][1];
        }

        float lf0 = bf2, lf1 = bf2;
#pragma unroll
        for (int c = 0; c < 8; c++) {
            const float* wr = wf1 + c * 8;
            float a0 = bf1[c], a1 = bf1[c];
#pragma unroll
            for (int k = 0; k < 8; k++) {
                const float w = wr[k];
                a0 = fmaf(w, x2e[k][0], a0);
                a1 = fmaf(w, x2e[k][1], a1);
            }
            const float wo = wf2[c];
            lf0 = fmaf(wo, fmaxf(a0, 0.0f), lf0);
            lf1 = fmaf(wo, fmaxf(a1, 0.0f), lf1);
        }

        sl[0][srow][c0]     = lb[0];
        sl[0][srow][c0 + 1] = lb[1];
        sl[1][srow][c0]     = le[0];
        sl[1][srow][c0 + 1] = le[1];
        sl[2][srow][c0]     = lf0;
        sl[2][srow][c0 + 1] = lf1;
    }
    __syncthreads();

    // ---------------- Phase C: aligned_bilinear x2 + sigmoid -----------------
    const int rows_here = min(OT, OH - i0);
    const int npix      = rows_here * OW;
    const long long ostride = (long long)n_inst * OH * OW;
    float* ob = out + (long long)inst * (OH * OW);

    for (int idx = tid; idx < npix; idx += 256) {
        const int di = idx / OW;
        const int j  = idx - di * OW;
        const int i  = i0 + di;
        const int r  = (i > 0) ? i - 1 : 0;
        const int c  = (j > 0) ? j - 1 : 0;
        const int y0 = r >> 1;
        const int x0 = c >> 1;
        const float fy = (r & 1) ? 0.5f : 0.0f;
        const float fx = (c & 1) ? 0.5f : 0.0f;
        const int y1  = min(y0 + 1, Hh - 1);
        const int x1c = min(x0 + 1, Wd - 1);
        const int s0 = y0 - ybase;
        const int s1 = y1 - ybase;
        const int oidx = i * OW + j;

#pragma unroll
        for (int m = 0; m < 3; m++) {
            const float v00 = sl[m][s0][x0],  v01 = sl[m][s0][x1c];
            const float v10 = sl[m][s1][x0],  v11 = sl[m][s1][x1c];
            const float vt = v00 + fx * (v01 - v00);
            const float vb = v10 + fx * (v11 - v10);
            const float v  = vt + fy * (vb - vt);
            ob[m * ostride + oidx] = __fdividef(1.0f, 1.0f + __expf(-v));
        }
    }
}

extern "C" void kernel_launch(void* const* d_in, const int* in_sizes, int n_in,
                              void* d_out, int out_size)
{
    const float* feats_b = (const float*)d_in[0];
    const float* feats_e = (const float*)d_in[1];
    const float* params  = (const float*)d_in[2];
    const float* locs    = (const float*)d_in[3];
    const float* soi     = (const float*)d_in[4];
    const int*   im      = (const int*)d_in[5];
    const int*   fpn     = (const int*)d_in[6];
    const int*   stridep = (n_in > 7) ? (const int*)d_in[7] : nullptr;

    const int n_inst = in_sizes[5];                 // 128 (im_inds count)
    dim3 grid((OH + OT - 1) / OT, n_inst);          // 13 x 128
    dmh_kernel<<<grid, 256>>>(feats_b, feats_e, params, locs, soi,
                              im, fpn, stridep, (float*)d_out, n_inst);
}

// round 3
// speedup vs baseline: 1.1448x; 1.1448x over previous
#include <cuda_runtime.h>
#include <cuda_bf16.h>

// DynamicMaskHead fused kernel (R3):
//   P=4 column blocking, heads computed in sequential passes with body-head
//   activations staged in per-thread smem scratch (kills register pressure
//   that caused R1's 255 regs / R2's spills).
//
// Shapes (fixed): feats [2,8,100,152] f32, params [128,419] f32,
//                 out = 3 x [128,1,200,304] f32 concatenated (b,e,f).

#define Hh   100
#define Wd   152
#define HWd  15200
#define OH   200
#define OW   304
#define OT   16      // output rows per block tile
#define LR   10      // logits rows per tile (8 + halo)
#define NPAR 419
#define NT   128     // threads per block

__global__ void __launch_bounds__(NT, 4)
dmh_kernel(const float* __restrict__ feats_b,
           const float* __restrict__ feats_e,
           const float* __restrict__ params,
           const float* __restrict__ locs,
           const float* __restrict__ soi_arr,
           const int*   __restrict__ im_inds,
           const int*   __restrict__ fpn,
           const int*   __restrict__ stride_ptr,
           float*       __restrict__ out,
           int n_inst)
{
    const int tid  = threadIdx.x;
    const int tile = blockIdx.x;
    const int inst = blockIdx.y;
    const int i0   = tile * OT;

    __shared__ float sp[NPAR];
    __shared__ float sl[3][LR][Wd];
    __shared__ float sxs[32][NT];     // per-thread scratch: x2b[8 ch][4 pos]

    const float* prow = params + inst * NPAR;
    for (int t = tid; t < NPAR; t += NT) sp[t] = prow[t];

    const int   stride  = stride_ptr ? *stride_ptr : 8;
    const float fstride = (float)stride;
    const float halfs   = (float)(stride >> 1);

    const float ix  = locs[inst * 2 + 0];
    const float iy  = locs[inst * 2 + 1];
    const float inv = 1.0f / soi_arr[fpn[inst]];
    const int   im  = im_inds[inst];

    const int ybase = max(0, 8 * tile - 1);
    const int yend  = min(Hh - 1, 8 * tile + 8);
    const int nrows = yend - ybase + 1;

    __syncthreads();

    const float* w1b = sp;       const float* w2b = sp + 80;  const float* w3b = sp + 144;
    const float* b1b = sp + 152; const float* b2b = sp + 160; const float  b3b = sp[168];
    const float* w1e = sp + 169; const float* w2e = sp + 249; const float* w3e = sp + 313;
    const float* b1e = sp + 321; const float* b2e = sp + 329; const float  b3e = sp[337];
    const float* wf1 = sp + 338; const float* wf2 = sp + 402; const float* bf1 = sp + 410;
    const float  bf2 = sp[418];

    const float* fbB = feats_b + (long long)im * 8 * HWd;
    const float* fbE = feats_e + (long long)im * 8 * HWd;

    // ---------------- Phase B: logits strip into smem ----------------
    const int ngroups = nrows * (Wd / 4);      // 38 col-groups per row
    for (int g = tid; g < ngroups; g += NT) {
        const int srow = g / 38;
        const int c0   = (g - srow * 38) * 4;
        const int y    = ybase + srow;

        const float rely = (iy - ((float)y * fstride + halfs)) * inv;
        float relx[4];
#pragma unroll
        for (int p = 0; p < 4; p++)
            relx[p] = (ix - ((float)(c0 + p) * fstride + halfs)) * inv;

        const int base = y * Wd + c0;

        // ============ PASS 1: body head ============
        {
            float4 f[8];
#pragma unroll
            for (int k = 0; k < 8; k++)
                f[k] = *(const float4*)(fbB + k * HWd + base);

            float x1[8][4];
#pragma unroll
            for (int c = 0; c < 8; c++) {
                const float* wr = w1b + c * 10;
                float a[4];
#pragma unroll
                for (int p = 0; p < 4; p++)
                    a[p] = fmaf(wr[0], relx[p], fmaf(wr[1], rely, b1b[c]));
#pragma unroll
                for (int k = 0; k < 8; k++) {
                    const float w = wr[2 + k];
                    a[0] = fmaf(w, f[k].x, a[0]);
                    a[1] = fmaf(w, f[k].y, a[1]);
                    a[2] = fmaf(w, f[k].z, a[2]);
                    a[3] = fmaf(w, f[k].w, a[3]);
                }
#pragma unroll
                for (int p = 0; p < 4; p++) x1[c][p] = fmaxf(a[p], 0.0f);
            }
            float lb[4] = {b3b, b3b, b3b, b3b};
#pragma unroll
            for (int c = 0; c < 8; c++) {
                const float* wr = w2b + c * 8;
                float a[4];
#pragma unroll
                for (int p = 0; p < 4; p++) a[p] = b2b[c];
#pragma unroll
                for (int k = 0; k < 8; k++) {
                    const float w = wr[k];
#pragma unroll
                    for (int p = 0; p < 4; p++) a[p] = fmaf(w, x1[k][p], a[p]);
                }
                const float wo = w3b[c];
#pragma unroll
                for (int p = 0; p < 4; p++) {
                    const float r = fmaxf(a[p], 0.0f);
                    sxs[c * 4 + p][tid] = r;          // stage x2b
                    lb[p] = fmaf(wo, r, lb[p]);
                }
            }
#pragma unroll
            for (int p = 0; p < 4; p++) sl[0][srow][c0 + p] = lb[p];
        }

        // ============ PASS 2: edge head (+ fused head) ============
        {
            float4 f[8];
#pragma unroll
            for (int k = 0; k < 8; k++)
                f[k] = *(const float4*)(fbE + k * HWd + base);

            float x1[8][4];
#pragma unroll
            for (int c = 0; c < 8; c++) {
                const float* wr = w1e + c * 10;
                float a[4];
#pragma unroll
                for (int p = 0; p < 4; p++)
                    a[p] = fmaf(wr[0], relx[p], fmaf(wr[1], rely, b1e[c]));
#pragma unroll
                for (int k = 0; k < 8; k++) {
                    const float w = wr[2 + k];
                    a[0] = fmaf(w, f[k].x, a[0]);
                    a[1] = fmaf(w, f[k].y, a[1]);
                    a[2] = fmaf(w, f[k].z, a[2]);
                    a[3] = fmaf(w, f[k].w, a[3]);
                }
#pragma unroll
                for (int p = 0; p < 4; p++) x1[c][p] = fmaxf(a[p], 0.0f);
            }
            float xf[8][4];     // becomes x2e + x2b (fused-head input)
            float le[4] = {b3e, b3e, b3e, b3e};
#pragma unroll
            for (int c = 0; c < 8; c++) {
                const float* wr = w2e + c * 8;
                float a[4];
#pragma unroll
                for (int p = 0; p < 4; p++) a[p] = b2e[c];
#pragma unroll
                for (int k = 0; k < 8; k++) {
                    const float w = wr[k];
#pragma unroll
                    for (int p = 0; p < 4; p++) a[p] = fmaf(w, x1[k][p], a[p]);
                }
                const float wo = w3e[c];
#pragma unroll
                for (int p = 0; p < 4; p++) {
                    const float r = fmaxf(a[p], 0.0f);
                    le[p] = fmaf(wo, r, le[p]);
                    xf[c][p] = r + sxs[c * 4 + p][tid];   // x2e + x2b
                }
            }
#pragma unroll
            for (int p = 0; p < 4; p++) sl[1][srow][c0 + p] = le[p];

            // fused head: 8 -> 8 (relu) -> 1
            float lf[4] = {bf2, bf2, bf2, bf2};
#pragma unroll
            for (int c = 0; c < 8; c++) {
                const float* wr = wf1 + c * 8;
                float a[4];
#pragma unroll
                for (int p = 0; p < 4; p++) a[p] = bf1[c];
#pragma unroll
                for (int k = 0; k < 8; k++) {
                    const float w = wr[k];
#pragma unroll
                    for (int p = 0; p < 4; p++) a[p] = fmaf(w, xf[k][p], a[p]);
                }
                const float wo = wf2[c];
#pragma unroll
                for (int p = 0; p < 4; p++)
                    lf[p] = fmaf(wo, fmaxf(a[p], 0.0f), lf[p]);
            }
#pragma unroll
            for (int p = 0; p < 4; p++) sl[2][srow][c0 + p] = lf[p];
        }
    }
    __syncthreads();

    // ---------------- Phase C: aligned_bilinear x2 + sigmoid ----------------
    const int rows_here = min(OT, OH - i0);
    const int npix      = rows_here * OW;
    const long long ostride = (long long)n_inst * OH * OW;
    float* ob = out + (long long)inst * (OH * OW);

    for (int idx = tid; idx < npix; idx += NT) {
        const int di = idx / OW;
        const int j  = idx - di * OW;
        const int i  = i0 + di;
        const int r  = (i > 0) ? i - 1 : 0;
        const int c  = (j > 0) ? j - 1 : 0;
        const int y0 = r >> 1;
        const int x0 = c >> 1;
        const float fy = (r & 1) ? 0.5f : 0.0f;
        const float fx = (c & 1) ? 0.5f : 0.0f;
        const int y1  = min(y0 + 1, Hh - 1);
        const int x1c = min(x0 + 1, Wd - 1);
        const int s0 = y0 - ybase;
        const int s1 = y1 - ybase;
        const int oidx = i * OW + j;

#pragma unroll
        for (int m = 0; m < 3; m++) {
            const float v00 = sl[m][s0][x0],  v01 = sl[m][s0][x1c];
            const float v10 = sl[m][s1][x0],  v11 = sl[m][s1][x1c];
            const float vt = v00 + fx * (v01 - v00);
            const float vb = v10 + fx * (v11 - v10);
            const float v  = vt + fy * (vb - vt);
            ob[m * ostride + oidx] = __fdividef(1.0f, 1.0f + __expf(-v));
        }
    }
}

extern "C" void kernel_launch(void* const* d_in, const int* in_sizes, int n_in,
                              void* d_out, int out_size)
{
    const float* feats_b = (const float*)d_in[0];
    const float* feats_e = (const float*)d_in[1];
    const float* params  = (const float*)d_in[2];
    const float* locs    = (const float*)d_in[3];
    const float* soi     = (const float*)d_in[4];
    const int*   im      = (const int*)d_in[5];
    const int*   fpn     = (const int*)d_in[6];
    const int*   stridep = (n_in > 7) ? (const int*)d_in[7] : nullptr;

    const int n_inst = in_sizes[5];                 // 128
    dim3 grid((OH + OT - 1) / OT, n_inst);          // 13 x 128
    dmh_kernel<<<grid, NT>>>(feats_b, feats_e, params, locs, soi,
                             im, fpn, stridep, (float*)d_out, n_inst);
}

// round 5
// speedup vs baseline: 1.5977x; 1.3956x over previous
#include <cuda_runtime.h>
#include <cuda_bf16.h>

// DynamicMaskHead fused kernel (R5):
//   P=4 column blocking, sequential head passes with smem staging of body
//   activations; reg cap 170 (launch_bounds 128,3) -> 3 CTAs/SM without the
//   spills the 128-reg cap caused in R2/R3. OT=24 keeps static smem at
//   43.7 KB (< 48 KB limit; R4's OT=40 exceeded it) with ~17% halo.
//
// Shapes (fixed): feats [2,8,100,152] f32, params [128,419] f32,
//                 out = 3 x [128,1,200,304] f32 concatenated (b,e,f).

#define Hh   100
#define Wd   152
#define HWd  15200
#define OH   200
#define OW   304
#define OT   24      // output rows per block tile (9 tiles)
#define LR   14      // max logits rows per tile (12 + 2 halo)
#define NPAR 419
#define NT   128     // threads per block

__global__ void __launch_bounds__(NT, 3)
dmh_kernel(const float* __restrict__ feats_b,
           const float* __restrict__ feats_e,
           const float* __restrict__ params,
           const float* __restrict__ locs,
           const float* __restrict__ soi_arr,
           const int*   __restrict__ im_inds,
           const int*   __restrict__ fpn,
           const int*   __restrict__ stride_ptr,
           float*       __restrict__ out,
           int n_inst)
{
    const int tid  = threadIdx.x;
    const int tile = blockIdx.x;
    const int inst = blockIdx.y;
    const int i0   = tile * OT;

    __shared__ float sp[NPAR];
    __shared__ float sl[3][LR][Wd];
    __shared__ float sxs[32][NT];     // per-thread scratch: x2b[8 ch][4 pos]

    const float* prow = params + inst * NPAR;
    for (int t = tid; t < NPAR; t += NT) sp[t] = prow[t];

    const int   stride  = stride_ptr ? *stride_ptr : 8;
    const float fstride = (float)stride;
    const float halfs   = (float)(stride >> 1);

    const float ix  = locs[inst * 2 + 0];
    const float iy  = locs[inst * 2 + 1];
    const float inv = 1.0f / soi_arr[fpn[inst]];
    const int   im  = im_inds[inst];

    // logits rows needed for output rows [i0, i0+OT)
    const int ybase = (i0 > 0) ? ((i0 - 1) >> 1) : 0;
    const int yend  = min(Hh - 1, ((i0 + OT - 2) >> 1) + 1);
    const int nrows = yend - ybase + 1;

    __syncthreads();

    const float* w1b = sp;       const float* w2b = sp + 80;  const float* w3b = sp + 144;
    const float* b1b = sp + 152; const float* b2b = sp + 160; const float  b3b = sp[168];
    const float* w1e = sp + 169; const float* w2e = sp + 249; const float* w3e = sp + 313;
    const float* b1e = sp + 321; const float* b2e = sp + 329; const float  b3e = sp[337];
    const float* wf1 = sp + 338; const float* wf2 = sp + 402; const float* bf1 = sp + 410;
    const float  bf2 = sp[418];

    const float* fbB = feats_b + (long long)im * 8 * HWd;
    const float* fbE = feats_e + (long long)im * 8 * HWd;

    // ---------------- Phase B: logits strip into smem ----------------
    const int ngroups = nrows * (Wd / 4);      // 38 col-groups per row
    for (int g = tid; g < ngroups; g += NT) {
        const int srow = g / 38;
        const int c0   = (g - srow * 38) * 4;
        const int y    = ybase + srow;

        const float rely = (iy - ((float)y * fstride + halfs)) * inv;
        float relx[4];
#pragma unroll
        for (int p = 0; p < 4; p++)
            relx[p] = (ix - ((float)(c0 + p) * fstride + halfs)) * inv;

        const int base = y * Wd + c0;

        // ============ PASS 1: body head ============
        {
            float4 f[8];
#pragma unroll
            for (int k = 0; k < 8; k++)
                f[k] = *(const float4*)(fbB + k * HWd + base);

            float x1[8][4];
#pragma unroll
            for (int c = 0; c < 8; c++) {
                const float* wr = w1b + c * 10;
                float a[4];
#pragma unroll
                for (int p = 0; p < 4; p++)
                    a[p] = fmaf(wr[0], relx[p], fmaf(wr[1], rely, b1b[c]));
#pragma unroll
                for (int k = 0; k < 8; k++) {
                    const float w = wr[2 + k];
                    a[0] = fmaf(w, f[k].x, a[0]);
                    a[1] = fmaf(w, f[k].y, a[1]);
                    a[2] = fmaf(w, f[k].z, a[2]);
                    a[3] = fmaf(w, f[k].w, a[3]);
                }
#pragma unroll
                for (int p = 0; p < 4; p++) x1[c][p] = fmaxf(a[p], 0.0f);
            }
            float lb[4] = {b3b, b3b, b3b, b3b};
#pragma unroll
            for (int c = 0; c < 8; c++) {
                const float* wr = w2b + c * 8;
                float a[4];
#pragma unroll
                for (int p = 0; p < 4; p++) a[p] = b2b[c];
#pragma unroll
                for (int k = 0; k < 8; k++) {
                    const float w = wr[k];
#pragma unroll
                    for (int p = 0; p < 4; p++) a[p] = fmaf(w, x1[k][p], a[p]);
                }
                const float wo = w3b[c];
#pragma unroll
                for (int p = 0; p < 4; p++) {
                    const float r = fmaxf(a[p], 0.0f);
                    sxs[c * 4 + p][tid] = r;          // stage x2b
                    lb[p] = fmaf(wo, r, lb[p]);
                }
            }
#pragma unroll
            for (int p = 0; p < 4; p++) sl[0][srow][c0 + p] = lb[p];
        }

        // ============ PASS 2: edge head (+ fused head) ============
        {
            float4 f[8];
#pragma unroll
            for (int k = 0; k < 8; k++)
                f[k] = *(const float4*)(fbE + k * HWd + base);

            float x1[8][4];
#pragma unroll
            for (int c = 0; c < 8; c++) {
                const float* wr = w1e + c * 10;
                float a[4];
#pragma unroll
                for (int p = 0; p < 4; p++)
                    a[p] = fmaf(wr[0], relx[p], fmaf(wr[1], rely, b1e[c]));
#pragma unroll
                for (int k = 0; k < 8; k++) {
                    const float w = wr[2 + k];
                    a[0] = fmaf(w, f[k].x, a[0]);
                    a[1] = fmaf(w, f[k].y, a[1]);
                    a[2] = fmaf(w, f[k].z, a[2]);
                    a[3] = fmaf(w, f[k].w, a[3]);
                }
#pragma unroll
                for (int p = 0; p < 4; p++) x1[c][p] = fmaxf(a[p], 0.0f);
            }
            float xf[8][4];     // becomes x2e + x2b (fused-head input)
            float le[4] = {b3e, b3e, b3e, b3e};
#pragma unroll
            for (int c = 0; c < 8; c++) {
                const float* wr = w2e + c * 8;
                float a[4];
#pragma unroll
                for (int p = 0; p < 4; p++) a[p] = b2e[c];
#pragma unroll
                for (int k = 0; k < 8; k++) {
                    const float w = wr[k];
#pragma unroll
                    for (int p = 0; p < 4; p++) a[p] = fmaf(w, x1[k][p], a[p]);
                }
                const float wo = w3e[c];
#pragma unroll
                for (int p = 0; p < 4; p++) {
                    const float r = fmaxf(a[p], 0.0f);
                    le[p] = fmaf(wo, r, le[p]);
                    xf[c][p] = r + sxs[c * 4 + p][tid];   // x2e + x2b
                }
            }
#pragma unroll
            for (int p = 0; p < 4; p++) sl[1][srow][c0 + p] = le[p];

            // fused head: 8 -> 8 (relu) -> 1
            float lf[4] = {bf2, bf2, bf2, bf2};
#pragma unroll
            for (int c = 0; c < 8; c++) {
                const float* wr = wf1 + c * 8;
                float a[4];
#pragma unroll
                for (int p = 0; p < 4; p++) a[p] = bf1[c];
#pragma unroll
                for (int k = 0; k < 8; k++) {
                    const float w = wr[k];
#pragma unroll
                    for (int p = 0; p < 4; p++) a[p] = fmaf(w, xf[k][p], a[p]);
                }
                const float wo = wf2[c];
#pragma unroll
                for (int p = 0; p < 4; p++)
                    lf[p] = fmaf(wo, fmaxf(a[p], 0.0f), lf[p]);
            }
#pragma unroll
            for (int p = 0; p < 4; p++) sl[2][srow][c0 + p] = lf[p];
        }
    }
    __syncthreads();

    // ---------------- Phase C: aligned_bilinear x2 + sigmoid ----------------
    const int rows_here = min(OT, OH - i0);
    const int npix      = rows_here * OW;
    const long long ostride = (long long)n_inst * OH * OW;
    float* ob = out + (long long)inst * (OH * OW);

    for (int idx = tid; idx < npix; idx += NT) {
        const int di = idx / OW;
        const int j  = idx - di * OW;
        const int i  = i0 + di;
        const int r  = (i > 0) ? i - 1 : 0;
        const int c  = (j > 0) ? j - 1 : 0;
        const int y0 = r >> 1;
        const int x0 = c >> 1;
        const float fy = (r & 1) ? 0.5f : 0.0f;
        const float fx = (c & 1) ? 0.5f : 0.0f;
        const int y1  = min(y0 + 1, Hh - 1);
        const int x1c = min(x0 + 1, Wd - 1);
        const int s0 = y0 - ybase;
        const int s1 = y1 - ybase;
        const int oidx = i * OW + j;

#pragma unroll
        for (int m = 0; m < 3; m++) {
            const float v00 = sl[m][s0][x0],  v01 = sl[m][s0][x1c];
            const float v10 = sl[m][s1][x0],  v11 = sl[m][s1][x1c];
            const float vt = v00 + fx * (v01 - v00);
            const float vb = v10 + fx * (v11 - v10);
            const float v  = vt + fy * (vb - vt);
            ob[m * ostride + oidx] = __fdividef(1.0f, 1.0f + __expf(-v));
        }
    }
}

extern "C" void kernel_launch(void* const* d_in, const int* in_sizes, int n_in,
                              void* d_out, int out_size)
{
    const float* feats_b = (const float*)d_in[0];
    const float* feats_e = (const float*)d_in[1];
    const float* params  = (const float*)d_in[2];
    const float* locs    = (const float*)d_in[3];
    const float* soi     = (const float*)d_in[4];
    const int*   im      = (const int*)d_in[5];
    const int*   fpn     = (const int*)d_in[6];
    const int*   stridep = (n_in > 7) ? (const int*)d_in[7] : nullptr;

    const int n_inst = in_sizes[5];                 // 128
    dim3 grid((OH + OT - 1) / OT, n_inst);          // 9 x 128
    dmh_kernel<<<grid, NT>>>(feats_b, feats_e, params, locs, soi,
                             im, fpn, stridep, (float*)d_out, n_inst);
}